// round 10
// baseline (speedup 1.0000x reference)
#include <cuda_runtime.h>
#include <cuda_fp16.h>
#include <math.h>

#define NNODES 100000
#define NEDGES 1600000
#define ETOT   (NEDGES + NNODES)
#define F      128
#define NG     128
#define NC     10
#define SCAN_B 1024
#define NSB    ((NNODES + SCAN_B - 1) / SCAN_B)
#define NB     64      // nodes per GEMM block
#define XPAD   66      // transposed-x row pad (8B alignment + reduced conflicts)

// ---------------- scratch (device globals; no allocation allowed) -------------
__device__ __align__(256) int   g_deg[NNODES];
__device__ __align__(256) int   g_off[NNODES + 1];
__device__ __align__(256) int   g_cur[NNODES];
__device__ __align__(256) float g_dis[NNODES];
__device__ __align__(256) int   g_ccol[ETOT];
__device__ __align__(256) float g_cnrm[ETOT];
__device__ __align__(256) __half g_h[(size_t)NNODES * F];   // fp16 gemm output (gather operand)
__device__ __align__(256) __half g_x[(size_t)NNODES * F];   // fp16 agg output (gemm/pool input)
__device__ int g_bs[NSB];
__device__ int g_flags[2];

// ---------------- stream/events for fork-join overlap (created pre-main) -----
static cudaStream_t s2;
static cudaEvent_t evFork, evJoin;
struct StreamInit {
    StreamInit() {
        cudaStreamCreateWithFlags(&s2, cudaStreamNonBlocking);
        cudaEventCreateWithFlags(&evFork, cudaEventDisableTiming);
        cudaEventCreateWithFlags(&evJoin, cudaEventDisableTiming);
    }
};
static StreamInit s_init;

// ---------------- f32x2 helpers (packed fp32: 2x FFMA rate) ------------------
__device__ __forceinline__ unsigned long long pack2(float x) {
    unsigned long long r;
    asm("mov.b64 %0, {%1, %1};" : "=l"(r) : "f"(x));
    return r;
}
__device__ __forceinline__ void ffma2(unsigned long long& d, unsigned long long a,
                                      unsigned long long b) {
    asm("fma.rn.f32x2 %0, %1, %2, %0;" : "+l"(d) : "l"(a), "l"(b));
}
__device__ __forceinline__ float lo32(unsigned long long v) { return __uint_as_float((unsigned)v); }
__device__ __forceinline__ float hi32(unsigned long long v) { return __uint_as_float((unsigned)(v >> 32)); }

__device__ __forceinline__ float4 h4_from_u2(uint2 r) {
    __half2 a = *reinterpret_cast<__half2*>(&r.x);
    __half2 b = *reinterpret_cast<__half2*>(&r.y);
    float2 f0 = __half22float2(a);
    float2 f1 = __half22float2(b);
    return make_float4(f0.x, f0.y, f1.x, f1.y);
}

// ---------------- helpers ----------------------------------------------------
__device__ __forceinline__ int load_idx(const void* p, long long i, int is64) {
    return is64 ? (int)(((const long long*)p)[i]) : ((const int*)p)[i];
}

// dtype detection + deg init (merged); see round-1 notes on the detection logic.
__global__ void k_detect(const void* ei, const void* batch) {
    __shared__ int s_bad;
    if (threadIdx.x == 0) s_bad = 0;
    __syncthreads();
    for (int i = threadIdx.x; i < NNODES; i += blockDim.x) g_deg[i] = 1;  // self-loops
    const int* b32 = (const int*)batch;
    int bad = 0;
    for (int j = threadIdx.x; j < NNODES - 1; j += blockDim.x) {
        int a = b32[j], c = b32[j + 1];
        if (a < 0 || a >= NG || c < a) { bad = 1; break; }
    }
    if (bad) atomicExch(&s_bad, 1);
    __syncthreads();
    if (threadIdx.x == 0) {
        g_flags[1] = s_bad ? 1 : 0;
        const long long* p = (const long long*)ei;
        int ok = 1;
        for (int i = 0; i < 64; i++) {
            long long v = p[(long long)i * 317 + 1];
            if (v < 0 || v >= NNODES) { ok = 0; break; }
        }
        g_flags[0] = ok;
    }
}

// 4 edges/thread with vector loads
__global__ void k_hist(const void* ei) {
    int is64 = g_flags[0];
    int i4 = (blockIdx.x * blockDim.x + threadIdx.x) * 4;
    if (i4 >= NEDGES) return;
    int r[4];
    if (i4 + 4 <= NEDGES) {
        if (is64) {
            longlong2 a = ((const longlong2*)ei)[i4 >> 1];
            longlong2 b = ((const longlong2*)ei)[(i4 >> 1) + 1];
            r[0] = (int)a.x; r[1] = (int)a.y; r[2] = (int)b.x; r[3] = (int)b.y;
        } else {
            int4 a = ((const int4*)ei)[i4 >> 2];
            r[0] = a.x; r[1] = a.y; r[2] = a.z; r[3] = a.w;
        }
#pragma unroll
        for (int u = 0; u < 4; u++) atomicAdd(&g_deg[r[u]], 1);
    } else {
        for (int i = i4; i < NEDGES; i++) atomicAdd(&g_deg[load_idx(ei, i, is64)], 1);
    }
}

__global__ void k_scan1() {
    __shared__ int s[SCAN_B];
    int i = blockIdx.x * SCAN_B + threadIdx.x;
    int v = (i < NNODES) ? g_deg[i] : 0;
    s[threadIdx.x] = v;
    __syncthreads();
    for (int d = SCAN_B / 2; d > 0; d >>= 1) {
        if (threadIdx.x < d) s[threadIdx.x] += s[threadIdx.x + d];
        __syncthreads();
    }
    if (threadIdx.x == 0) g_bs[blockIdx.x] = s[0];
}

__global__ void k_scan2() {
    if (threadIdx.x == 0 && blockIdx.x == 0) {
        int run = 0;
        for (int b = 0; b < NSB; b++) { int t = g_bs[b]; g_bs[b] = run; run += t; }
        g_off[NNODES] = run;
    }
}

__global__ void k_scan3() {
    __shared__ int s[SCAN_B];
    int tid = threadIdx.x;
    int i = blockIdx.x * SCAN_B + tid;
    int v = (i < NNODES) ? g_deg[i] : 0;
    s[tid] = v;
    __syncthreads();
    for (int d = 1; d < SCAN_B; d <<= 1) {
        int t = (tid >= d) ? s[tid - d] : 0;
        __syncthreads();
        s[tid] += t;
        __syncthreads();
    }
    if (i < NNODES) {
        int excl = s[tid] - v + g_bs[blockIdx.x];
        g_off[i] = excl;
        g_cur[i] = excl;
        g_dis[i] = rsqrtf((float)v + 1e-12f);
    }
}

// 2 edges/thread with vector loads
__global__ void k_fill(const void* ei) {
    int is64 = g_flags[0];
    int i2 = (blockIdx.x * blockDim.x + threadIdx.x) * 2;
    if (i2 < NEDGES) {
        int r0, r1, c0, c1;
        if (i2 + 2 <= NEDGES) {
            if (is64) {
                longlong2 rr = ((const longlong2*)ei)[i2 >> 1];
                longlong2 cc = ((const longlong2*)ei)[(NEDGES + i2) >> 1];
                r0 = (int)rr.x; r1 = (int)rr.y; c0 = (int)cc.x; c1 = (int)cc.y;
            } else {
                int2 rr = ((const int2*)ei)[i2 >> 1];
                int2 cc = ((const int2*)ei)[(NEDGES + i2) >> 1];
                r0 = rr.x; r1 = rr.y; c0 = cc.x; c1 = cc.y;
            }
            int p0 = atomicAdd(&g_cur[r0], 1);
            g_ccol[p0] = c0;
            g_cnrm[p0] = g_dis[r0] * g_dis[c0];
            int p1 = atomicAdd(&g_cur[r1], 1);
            g_ccol[p1] = c1;
            g_cnrm[p1] = g_dis[r1] * g_dis[c1];
        } else {
            for (int i = i2; i < NEDGES; i++) {
                int r = load_idx(ei, i, is64);
                int c = load_idx(ei, (long long)NEDGES + i, is64);
                int p = atomicAdd(&g_cur[r], 1);
                g_ccol[p] = c;
                g_cnrm[p] = g_dis[r] * g_dis[c];
            }
        }
    }
}

__global__ void k_fill_loops() {
    int i = blockIdx.x * blockDim.x + threadIdx.x;
    if (i < NNODES) {
        int p = atomicAdd(&g_cur[i], 1);
        g_ccol[p] = i;
        float d = g_dis[i];
        g_cnrm[p] = d * d;
    }
}

// ---------------- GEMM with packed f32x2 FFMA; fp16 output -------------------
// HALF_IN: input activations stored fp16 (layers 2,3); fp32 for layer 1 (X).
template <bool HALF_IN>
__global__ __launch_bounds__(256, 2)
void k_gemm(const void* __restrict__ in, const float* __restrict__ W,
            const float* __restrict__ b, __half* __restrict__ out) {
    extern __shared__ float sm[];
    float* Ws = sm;                 // 128 x 128
    float* xs = sm + F * F;         // 128 x XPAD (transposed)

    const float4* W4 = (const float4*)W;
    float4* Ws4 = (float4*)Ws;
    for (int i = threadIdx.x; i < F * F / 4; i += 256) Ws4[i] = W4[i];

    int node0 = blockIdx.x * NB;
    for (int i = threadIdx.x; i < NB * 32; i += 256) {
        int n = i >> 5, kg = i & 31;
        int node = node0 + n;
        float4 v;
        if (node < NNODES) {
            if (HALF_IN) {
                uint2 raw = ((const uint2*)in)[(size_t)node * 32 + kg];
                v = h4_from_u2(raw);
            } else {
                v = ((const float4*)in)[(size_t)node * 32 + kg];
            }
        } else {
            v = make_float4(0.f, 0.f, 0.f, 0.f);
        }
        xs[(4 * kg + 0) * XPAD + n] = v.x;
        xs[(4 * kg + 1) * XPAD + n] = v.y;
        xs[(4 * kg + 2) * XPAD + n] = v.z;
        xs[(4 * kg + 3) * XPAD + n] = v.w;
    }
    __syncthreads();

    int warp = threadIdx.x >> 5, lane = threadIdx.x & 31;
    int nb = warp * 8;

    unsigned long long acc[4][4];
    {
        unsigned long long bb[4];
#pragma unroll
        for (int d = 0; d < 4; d++) bb[d] = pack2(b[4 * lane + d]);
#pragma unroll
        for (int p = 0; p < 4; p++)
#pragma unroll
            for (int d = 0; d < 4; d++) acc[p][d] = bb[d];
    }

#pragma unroll 4
    for (int j = 0; j < 32; j++) {
        float4 w0 = Ws4[(4 * j + 0) * 32 + lane];
        float4 w1 = Ws4[(4 * j + 1) * 32 + lane];
        float4 w2 = Ws4[(4 * j + 2) * 32 + lane];
        float4 w3 = Ws4[(4 * j + 3) * 32 + lane];
        unsigned long long wd[4][4];
        wd[0][0] = pack2(w0.x); wd[0][1] = pack2(w0.y); wd[0][2] = pack2(w0.z); wd[0][3] = pack2(w0.w);
        wd[1][0] = pack2(w1.x); wd[1][1] = pack2(w1.y); wd[1][2] = pack2(w1.z); wd[1][3] = pack2(w1.w);
        wd[2][0] = pack2(w2.x); wd[2][1] = pack2(w2.y); wd[2][2] = pack2(w2.z); wd[2][3] = pack2(w2.w);
        wd[3][0] = pack2(w3.x); wd[3][1] = pack2(w3.y); wd[3][2] = pack2(w3.z); wd[3][3] = pack2(w3.w);
#pragma unroll
        for (int p = 0; p < 4; p++) {
            int nidx = nb + 2 * p;
#pragma unroll
            for (int kk = 0; kk < 4; kk++) {
                unsigned long long a =
                    *(const unsigned long long*)&xs[(4 * j + kk) * XPAD + nidx];
                ffma2(acc[p][0], a, wd[kk][0]);
                ffma2(acc[p][1], a, wd[kk][1]);
                ffma2(acc[p][2], a, wd[kk][2]);
                ffma2(acc[p][3], a, wd[kk][3]);
            }
        }
    }

    uint2* out2 = (uint2*)out;
#pragma unroll
    for (int p = 0; p < 4; p++) {
        int n0 = node0 + nb + 2 * p;
        int n1 = n0 + 1;
        __half2 l01 = __floats2half2_rn(lo32(acc[p][0]), lo32(acc[p][1]));
        __half2 l23 = __floats2half2_rn(lo32(acc[p][2]), lo32(acc[p][3]));
        __half2 h01 = __floats2half2_rn(hi32(acc[p][0]), hi32(acc[p][1]));
        __half2 h23 = __floats2half2_rn(hi32(acc[p][2]), hi32(acc[p][3]));
        uint2 lv, hv;
        lv.x = *reinterpret_cast<unsigned*>(&l01);
        lv.y = *reinterpret_cast<unsigned*>(&l23);
        hv.x = *reinterpret_cast<unsigned*>(&h01);
        hv.y = *reinterpret_cast<unsigned*>(&h23);
        if (n0 < NNODES) out2[(size_t)n0 * 32 + lane] = lv;
        if (n1 < NNODES) out2[(size_t)n1 * 32 + lane] = hv;
    }
}

// ---------------- aggregation: 2 nodes/warp, joint gather loop ---------------
__device__ __forceinline__ void agg_rest(const uint2* __restrict__ h2, int lane,
                                         int e, int E, float4& A, float4& B) {
    for (; e + 8 <= E; e += 8) {
        int   c[8];
        float m[8];
#pragma unroll
        for (int u = 0; u < 8; u++) { c[u] = g_ccol[e + u]; m[u] = g_cnrm[e + u]; }
        uint2 raw[8];
#pragma unroll
        for (int u = 0; u < 8; u++) raw[u] = h2[(size_t)c[u] * 32 + lane];
#pragma unroll
        for (int u = 0; u < 8; u += 2) {
            float4 v0 = h4_from_u2(raw[u]);
            float4 v1 = h4_from_u2(raw[u + 1]);
            A.x = fmaf(m[u], v0.x, A.x);
            A.y = fmaf(m[u], v0.y, A.y);
            A.z = fmaf(m[u], v0.z, A.z);
            A.w = fmaf(m[u], v0.w, A.w);
            B.x = fmaf(m[u + 1], v1.x, B.x);
            B.y = fmaf(m[u + 1], v1.y, B.y);
            B.z = fmaf(m[u + 1], v1.z, B.z);
            B.w = fmaf(m[u + 1], v1.w, B.w);
        }
    }
    for (; e < E; e++) {
        int cc = g_ccol[e];
        float nrm = g_cnrm[e];
        float4 v = h4_from_u2(h2[(size_t)cc * 32 + lane]);
        A.x = fmaf(nrm, v.x, A.x);
        A.y = fmaf(nrm, v.y, A.y);
        A.z = fmaf(nrm, v.z, A.z);
        A.w = fmaf(nrm, v.w, A.w);
    }
}

__device__ __forceinline__ void agg_store(uint2* xo, int node, int lane,
                                          const float4& A, const float4& B) {
    __half2 p01 = __floats2half2_rn(fmaxf(A.x + B.x, 0.f), fmaxf(A.y + B.y, 0.f));
    __half2 p23 = __floats2half2_rn(fmaxf(A.z + B.z, 0.f), fmaxf(A.w + B.w, 0.f));
    uint2 v;
    v.x = *reinterpret_cast<unsigned*>(&p01);
    v.y = *reinterpret_cast<unsigned*>(&p23);
    xo[(size_t)node * 32 + lane] = v;
}

__global__ void k_agg(const __half* __restrict__ h, __half* __restrict__ xo) {
    int gw = (blockIdx.x * blockDim.x + threadIdx.x) >> 5;
    int lane = threadIdx.x & 31;
    int n0 = gw * 2, n1 = n0 + 1;
    if (n0 >= NNODES) return;
    bool has1 = (n1 < NNODES);
    const uint2* h2 = (const uint2*)h;
    uint2* xo2 = (uint2*)xo;

    int e0 = g_off[n0], E0 = g_off[n0 + 1];
    int e1 = has1 ? g_off[n1] : 0, E1 = has1 ? g_off[n1 + 1] : 0;

    float4 a0 = make_float4(0.f, 0.f, 0.f, 0.f), b0 = a0;
    float4 a1 = a0, b1 = a0;

    // joint loop: 4 edges from each node per iteration (8 independent gathers)
    while (e0 + 4 <= E0 && e1 + 4 <= E1) {
        int   c0[4], c1[4];
        float m0[4], m1[4];
#pragma unroll
        for (int u = 0; u < 4; u++) { c0[u] = g_ccol[e0 + u]; m0[u] = g_cnrm[e0 + u]; }
#pragma unroll
        for (int u = 0; u < 4; u++) { c1[u] = g_ccol[e1 + u]; m1[u] = g_cnrm[e1 + u]; }
        uint2 r0[4], r1[4];
#pragma unroll
        for (int u = 0; u < 4; u++) r0[u] = h2[(size_t)c0[u] * 32 + lane];
#pragma unroll
        for (int u = 0; u < 4; u++) r1[u] = h2[(size_t)c1[u] * 32 + lane];
#pragma unroll
        for (int u = 0; u < 4; u += 2) {
            float4 v0 = h4_from_u2(r0[u]);
            float4 v0b = h4_from_u2(r0[u + 1]);
            a0.x = fmaf(m0[u], v0.x, a0.x);
            a0.y = fmaf(m0[u], v0.y, a0.y);
            a0.z = fmaf(m0[u], v0.z, a0.z);
            a0.w = fmaf(m0[u], v0.w, a0.w);
            b0.x = fmaf(m0[u + 1], v0b.x, b0.x);
            b0.y = fmaf(m0[u + 1], v0b.y, b0.y);
            b0.z = fmaf(m0[u + 1], v0b.z, b0.z);
            b0.w = fmaf(m0[u + 1], v0b.w, b0.w);
            float4 v1 = h4_from_u2(r1[u]);
            float4 v1b = h4_from_u2(r1[u + 1]);
            a1.x = fmaf(m1[u], v1.x, a1.x);
            a1.y = fmaf(m1[u], v1.y, a1.y);
            a1.z = fmaf(m1[u], v1.z, a1.z);
            a1.w = fmaf(m1[u], v1.w, a1.w);
            b1.x = fmaf(m1[u + 1], v1b.x, b1.x);
            b1.y = fmaf(m1[u + 1], v1b.y, b1.y);
            b1.z = fmaf(m1[u + 1], v1b.z, b1.z);
            b1.w = fmaf(m1[u + 1], v1b.w, b1.w);
        }
        e0 += 4; e1 += 4;
    }
    agg_rest(h2, lane, e0, E0, a0, b0);
    if (has1) agg_rest(h2, lane, e1, E1, a1, b1);

    agg_store(xo2, n0, lane, a0, b0);
    if (has1) agg_store(xo2, n1, lane, a1, b1);
}

// ---------------- fused pool + MLP head --------------------------------------
__device__ __forceinline__ int lbound(const void* b, int is64, long long key) {
    int lo = 0, hi = NNODES;
    while (lo < hi) {
        int mid = (lo + hi) >> 1;
        long long v = is64 ? ((const long long*)b)[mid] : (long long)((const int*)b)[mid];
        if (v < key) lo = mid + 1; else hi = mid;
    }
    return lo;
}

__global__ void k_pool_mlp(const void* batch,
                           const float* __restrict__ Wm1, const float* __restrict__ bm1,
                           const float* __restrict__ Wm2, const float* __restrict__ bm2,
                           float* __restrict__ out) {
    __shared__ float gs[2 * F];
    __shared__ float hs[F];
    int g = blockIdx.x, tid = threadIdx.x;
    int is64 = g_flags[1];
    int s = lbound(batch, is64, g);
    int e = lbound(batch, is64, g + 1);
    float sum = 0.f, mx = -3.4e38f;
    int n = s;
    for (; n + 2 <= e; n += 2) {
        float v0 = __half2float(g_x[(size_t)n * F + tid]);
        float v1 = __half2float(g_x[(size_t)(n + 1) * F + tid]);
        sum += v0 + v1;
        mx = fmaxf(mx, fmaxf(v0, v1));
    }
    for (; n < e; n++) {
        float v = __half2float(g_x[(size_t)n * F + tid]);
        sum += v;
        mx = fmaxf(mx, v);
    }
    int cnt = e - s;
    gs[tid] = sum / ((float)cnt + 1e-12f);
    gs[F + tid] = (cnt == 0) ? 0.f : mx;
    __syncthreads();
    float acc = bm1[tid];
#pragma unroll 8
    for (int k = 0; k < 2 * F; k++) acc = fmaf(gs[k], Wm1[k * F + tid], acc);
    hs[tid] = fmaxf(acc, 0.f);
    __syncthreads();
    if (tid < NC) {
        float a = bm2[tid];
#pragma unroll 8
        for (int k = 0; k < F; k++) a = fmaf(hs[k], Wm2[k * NC + tid], a);
        out[g * NC + tid] = a;
    }
}

// ---------------- launch ------------------------------------------------------
extern "C" void kernel_launch(void* const* d_in, const int* in_sizes, int n_in,
                              void* d_out, int out_size) {
    int iX = -1, iEI = -1, iB = -1, iW[3] = {-1, -1, -1}, ibv[4] = {-1, -1, -1, -1};
    int nw = 0, nb = 0, iWm1 = -1, iWm2 = -1, ibm2 = -1;
    for (int i = 0; i < n_in; i++) {
        int s = in_sizes[i];
        if (s == NNODES * F) iX = i;
        else if (s == 2 * NEDGES) iEI = i;
        else if (s == NNODES) iB = i;
        else if (s == F * F) { if (nw < 3) iW[nw++] = i; }
        else if (s == F) { if (nb < 4) ibv[nb++] = i; }
        else if (s == 2 * F * F) iWm1 = i;
        else if (s == F * NC) iWm2 = i;
        else if (s == NC) ibm2 = i;
    }
    const float* X   = (const float*)d_in[iX];
    const void*  EI  = d_in[iEI];
    const void*  BT  = d_in[iB];
    const float* W1  = (const float*)d_in[iW[0]];
    const float* W2  = (const float*)d_in[iW[1]];
    const float* W3  = (const float*)d_in[iW[2]];
    const float* b1  = (const float*)d_in[ibv[0]];
    const float* b2  = (const float*)d_in[ibv[1]];
    const float* b3  = (const float*)d_in[ibv[2]];
    const float* bm1 = (const float*)d_in[ibv[3]];
    const float* Wm1 = (const float*)d_in[iWm1];
    const float* Wm2 = (const float*)d_in[iWm2];
    const float* bm2 = (const float*)d_in[ibm2];
    float* out = (float*)d_out;

    void *ph = nullptr, *px = nullptr;
    cudaGetSymbolAddress(&ph, g_h);
    cudaGetSymbolAddress(&px, g_x);
    __half* H = (__half*)ph;
    __half* Xb = (__half*)px;

    size_t shm = (size_t)(F * F + F * XPAD) * sizeof(float);
    cudaFuncSetAttribute(k_gemm<false>, cudaFuncAttributeMaxDynamicSharedMemorySize, (int)shm);
    cudaFuncSetAttribute(k_gemm<true>, cudaFuncAttributeMaxDynamicSharedMemorySize, (int)shm);

    int gemm_grid = (NNODES + NB - 1) / NB;
    int agg_grid = ((NNODES + 1) / 2 * 32 + 255) / 256;   // 2 nodes per warp

    // Fork: layer-1 GEMM (depends only on X/W1) on s2, concurrent with CSR build.
    cudaEventRecord(evFork, 0);
    cudaStreamWaitEvent(s2, evFork, 0);
    k_gemm<false><<<gemm_grid, 256, shm, s2>>>(X, W1, b1, H);
    cudaEventRecord(evJoin, s2);

    // CSR preprocessing on the main stream
    k_detect<<<1, 1024>>>(EI, BT);
    k_hist<<<(NEDGES / 4 + 255) / 256, 256>>>(EI);
    k_scan1<<<NSB, SCAN_B>>>();
    k_scan2<<<1, 32>>>();
    k_scan3<<<NSB, SCAN_B>>>();
    k_fill<<<(NEDGES / 2 + 255) / 256, 256>>>(EI);
    k_fill_loops<<<(NNODES + 255) / 256, 256>>>();

    cudaStreamWaitEvent(0, evJoin, 0);

    k_agg<<<agg_grid, 256>>>(H, Xb);
    k_gemm<true><<<gemm_grid, 256, shm>>>(Xb, W2, b2, H);
    k_agg<<<agg_grid, 256>>>(H, Xb);
    k_gemm<true><<<gemm_grid, 256, shm>>>(Xb, W3, b3, H);
    k_agg<<<agg_grid, 256>>>(H, Xb);

    k_pool_mlp<<<NG, F>>>(BT, Wm1, bm1, Wm2, bm2, out);
}

// round 13
// speedup vs baseline: 1.1253x; 1.1253x over previous
#include <cuda_runtime.h>
#include <cuda_fp16.h>
#include <math.h>

#define NNODES 100000
#define NEDGES 1600000
#define ETOT   (NEDGES + NNODES)
#define F      128
#define NG     128
#define NC     10
#define SCAN_B 1024
#define NSB    ((NNODES + SCAN_B - 1) / SCAN_B)
#define NB     64      // nodes per GEMM block
#define XPAD   66      // transposed-x row pad (8B alignment + reduced conflicts)

// ---------------- scratch (device globals; no allocation allowed) -------------
__device__ __align__(256) int   g_deg[NNODES];
__device__ __align__(256) int   g_off[NNODES + 1];
__device__ __align__(256) int   g_cur[NNODES];
__device__ __align__(256) float g_dis[NNODES];
__device__ __align__(256) int   g_ccol[ETOT];
__device__ __align__(256) float g_cnrm[ETOT];
__device__ __align__(256) __half g_h[(size_t)NNODES * F];   // fp16 gemm output (gather operand)
__device__ __align__(256) __half g_x[(size_t)NNODES * F];   // fp16 agg output (gemm/pool input)
__device__ int g_bs[NSB];
__device__ int g_flags[2];

// ---------------- stream/events for fork-join overlap (created pre-main) -----
static cudaStream_t s2;
static cudaEvent_t evFork, evJoin;
struct StreamInit {
    StreamInit() {
        cudaStreamCreateWithFlags(&s2, cudaStreamNonBlocking);
        cudaEventCreateWithFlags(&evFork, cudaEventDisableTiming);
        cudaEventCreateWithFlags(&evJoin, cudaEventDisableTiming);
    }
};
static StreamInit s_init;

// ---------------- f32x2 helpers (packed fp32: 2x FFMA rate) ------------------
__device__ __forceinline__ unsigned long long pack2(float x) {
    unsigned long long r;
    asm("mov.b64 %0, {%1, %1};" : "=l"(r) : "f"(x));
    return r;
}
__device__ __forceinline__ void ffma2(unsigned long long& d, unsigned long long a,
                                      unsigned long long b) {
    asm("fma.rn.f32x2 %0, %1, %2, %0;" : "+l"(d) : "l"(a), "l"(b));
}
__device__ __forceinline__ float lo32(unsigned long long v) { return __uint_as_float((unsigned)v); }
__device__ __forceinline__ float hi32(unsigned long long v) { return __uint_as_float((unsigned)(v >> 32)); }

__device__ __forceinline__ float4 h4_from_u2(uint2 r) {
    __half2 a = *reinterpret_cast<__half2*>(&r.x);
    __half2 b = *reinterpret_cast<__half2*>(&r.y);
    float2 f0 = __half22float2(a);
    float2 f1 = __half22float2(b);
    return make_float4(f0.x, f0.y, f1.x, f1.y);
}

// ---------------- helpers ----------------------------------------------------
__device__ __forceinline__ int load_idx(const void* p, long long i, int is64) {
    return is64 ? (int)(((const long long*)p)[i]) : ((const int*)p)[i];
}

// dtype detection + deg init (merged); see round-1 notes on the detection logic.
__global__ void k_detect(const void* ei, const void* batch) {
    __shared__ int s_bad;
    if (threadIdx.x == 0) s_bad = 0;
    __syncthreads();
    for (int i = threadIdx.x; i < NNODES; i += blockDim.x) g_deg[i] = 1;  // self-loops
    const int* b32 = (const int*)batch;
    int bad = 0;
    for (int j = threadIdx.x; j < NNODES - 1; j += blockDim.x) {
        int a = b32[j], c = b32[j + 1];
        if (a < 0 || a >= NG || c < a) { bad = 1; break; }
    }
    if (bad) atomicExch(&s_bad, 1);
    __syncthreads();
    if (threadIdx.x == 0) {
        g_flags[1] = s_bad ? 1 : 0;
        const long long* p = (const long long*)ei;
        int ok = 1;
        for (int i = 0; i < 64; i++) {
            long long v = p[(long long)i * 317 + 1];
            if (v < 0 || v >= NNODES) { ok = 0; break; }
        }
        g_flags[0] = ok;
    }
}

// 4 edges/thread with vector loads
__global__ void k_hist(const void* ei) {
    int is64 = g_flags[0];
    int i4 = (blockIdx.x * blockDim.x + threadIdx.x) * 4;
    if (i4 >= NEDGES) return;
    int r[4];
    if (i4 + 4 <= NEDGES) {
        if (is64) {
            longlong2 a = ((const longlong2*)ei)[i4 >> 1];
            longlong2 b = ((const longlong2*)ei)[(i4 >> 1) + 1];
            r[0] = (int)a.x; r[1] = (int)a.y; r[2] = (int)b.x; r[3] = (int)b.y;
        } else {
            int4 a = ((const int4*)ei)[i4 >> 2];
            r[0] = a.x; r[1] = a.y; r[2] = a.z; r[3] = a.w;
        }
#pragma unroll
        for (int u = 0; u < 4; u++) atomicAdd(&g_deg[r[u]], 1);
    } else {
        for (int i = i4; i < NEDGES; i++) atomicAdd(&g_deg[load_idx(ei, i, is64)], 1);
    }
}

__global__ void k_scan1() {
    __shared__ int s[SCAN_B];
    int i = blockIdx.x * SCAN_B + threadIdx.x;
    int v = (i < NNODES) ? g_deg[i] : 0;
    s[threadIdx.x] = v;
    __syncthreads();
    for (int d = SCAN_B / 2; d > 0; d >>= 1) {
        if (threadIdx.x < d) s[threadIdx.x] += s[threadIdx.x + d];
        __syncthreads();
    }
    if (threadIdx.x == 0) g_bs[blockIdx.x] = s[0];
}

__global__ void k_scan2() {
    if (threadIdx.x == 0 && blockIdx.x == 0) {
        int run = 0;
        for (int b = 0; b < NSB; b++) { int t = g_bs[b]; g_bs[b] = run; run += t; }
        g_off[NNODES] = run;
    }
}

__global__ void k_scan3() {
    __shared__ int s[SCAN_B];
    int tid = threadIdx.x;
    int i = blockIdx.x * SCAN_B + tid;
    int v = (i < NNODES) ? g_deg[i] : 0;
    s[tid] = v;
    __syncthreads();
    for (int d = 1; d < SCAN_B; d <<= 1) {
        int t = (tid >= d) ? s[tid - d] : 0;
        __syncthreads();
        s[tid] += t;
        __syncthreads();
    }
    if (i < NNODES) {
        int excl = s[tid] - v + g_bs[blockIdx.x];
        g_off[i] = excl;
        g_cur[i] = excl;
        g_dis[i] = rsqrtf((float)v + 1e-12f);
    }
}

// 2 edges/thread with vector loads
__global__ void k_fill(const void* ei) {
    int is64 = g_flags[0];
    int i2 = (blockIdx.x * blockDim.x + threadIdx.x) * 2;
    if (i2 < NEDGES) {
        int r0, r1, c0, c1;
        if (i2 + 2 <= NEDGES) {
            if (is64) {
                longlong2 rr = ((const longlong2*)ei)[i2 >> 1];
                longlong2 cc = ((const longlong2*)ei)[(NEDGES + i2) >> 1];
                r0 = (int)rr.x; r1 = (int)rr.y; c0 = (int)cc.x; c1 = (int)cc.y;
            } else {
                int2 rr = ((const int2*)ei)[i2 >> 1];
                int2 cc = ((const int2*)ei)[(NEDGES + i2) >> 1];
                r0 = rr.x; r1 = rr.y; c0 = cc.x; c1 = cc.y;
            }
            int p0 = atomicAdd(&g_cur[r0], 1);
            g_ccol[p0] = c0;
            g_cnrm[p0] = g_dis[r0] * g_dis[c0];
            int p1 = atomicAdd(&g_cur[r1], 1);
            g_ccol[p1] = c1;
            g_cnrm[p1] = g_dis[r1] * g_dis[c1];
        } else {
            for (int i = i2; i < NEDGES; i++) {
                int r = load_idx(ei, i, is64);
                int c = load_idx(ei, (long long)NEDGES + i, is64);
                int p = atomicAdd(&g_cur[r], 1);
                g_ccol[p] = c;
                g_cnrm[p] = g_dis[r] * g_dis[c];
            }
        }
    }
}

__global__ void k_fill_loops() {
    int i = blockIdx.x * blockDim.x + threadIdx.x;
    if (i < NNODES) {
        int p = atomicAdd(&g_cur[i], 1);
        g_ccol[p] = i;
        float d = g_dis[i];
        g_cnrm[p] = d * d;
    }
}

// ---------------- GEMM with packed f32x2 FFMA; fp16 output -------------------
// HALF_IN: input activations stored fp16 (layers 2,3); fp32 for layer 1 (X).
template <bool HALF_IN>
__global__ __launch_bounds__(256, 2)
void k_gemm(const void* __restrict__ in, const float* __restrict__ W,
            const float* __restrict__ b, __half* __restrict__ out) {
    extern __shared__ float sm[];
    float* Ws = sm;                 // 128 x 128
    float* xs = sm + F * F;         // 128 x XPAD (transposed)

    const float4* W4 = (const float4*)W;
    float4* Ws4 = (float4*)Ws;
    for (int i = threadIdx.x; i < F * F / 4; i += 256) Ws4[i] = W4[i];

    int node0 = blockIdx.x * NB;
    for (int i = threadIdx.x; i < NB * 32; i += 256) {
        int n = i >> 5, kg = i & 31;
        int node = node0 + n;
        float4 v;
        if (node < NNODES) {
            if (HALF_IN) {
                uint2 raw = ((const uint2*)in)[(size_t)node * 32 + kg];
                v = h4_from_u2(raw);
            } else {
                v = ((const float4*)in)[(size_t)node * 32 + kg];
            }
        } else {
            v = make_float4(0.f, 0.f, 0.f, 0.f);
        }
        xs[(4 * kg + 0) * XPAD + n] = v.x;
        xs[(4 * kg + 1) * XPAD + n] = v.y;
        xs[(4 * kg + 2) * XPAD + n] = v.z;
        xs[(4 * kg + 3) * XPAD + n] = v.w;
    }
    __syncthreads();

    int warp = threadIdx.x >> 5, lane = threadIdx.x & 31;
    int nb = warp * 8;

    unsigned long long acc[4][4];
    {
        unsigned long long bb[4];
#pragma unroll
        for (int d = 0; d < 4; d++) bb[d] = pack2(b[4 * lane + d]);
#pragma unroll
        for (int p = 0; p < 4; p++)
#pragma unroll
            for (int d = 0; d < 4; d++) acc[p][d] = bb[d];
    }

#pragma unroll 4
    for (int j = 0; j < 32; j++) {
        float4 w0 = Ws4[(4 * j + 0) * 32 + lane];
        float4 w1 = Ws4[(4 * j + 1) * 32 + lane];
        float4 w2 = Ws4[(4 * j + 2) * 32 + lane];
        float4 w3 = Ws4[(4 * j + 3) * 32 + lane];
        unsigned long long wd[4][4];
        wd[0][0] = pack2(w0.x); wd[0][1] = pack2(w0.y); wd[0][2] = pack2(w0.z); wd[0][3] = pack2(w0.w);
        wd[1][0] = pack2(w1.x); wd[1][1] = pack2(w1.y); wd[1][2] = pack2(w1.z); wd[1][3] = pack2(w1.w);
        wd[2][0] = pack2(w2.x); wd[2][1] = pack2(w2.y); wd[2][2] = pack2(w2.z); wd[2][3] = pack2(w2.w);
        wd[3][0] = pack2(w3.x); wd[3][1] = pack2(w3.y); wd[3][2] = pack2(w3.z); wd[3][3] = pack2(w3.w);
#pragma unroll
        for (int p = 0; p < 4; p++) {
            int nidx = nb + 2 * p;
#pragma unroll
            for (int kk = 0; kk < 4; kk++) {
                unsigned long long a =
                    *(const unsigned long long*)&xs[(4 * j + kk) * XPAD + nidx];
                ffma2(acc[p][0], a, wd[kk][0]);
                ffma2(acc[p][1], a, wd[kk][1]);
                ffma2(acc[p][2], a, wd[kk][2]);
                ffma2(acc[p][3], a, wd[kk][3]);
            }
        }
    }

    uint2* out2 = (uint2*)out;
#pragma unroll
    for (int p = 0; p < 4; p++) {
        int n0 = node0 + nb + 2 * p;
        int n1 = n0 + 1;
        __half2 l01 = __floats2half2_rn(lo32(acc[p][0]), lo32(acc[p][1]));
        __half2 l23 = __floats2half2_rn(lo32(acc[p][2]), lo32(acc[p][3]));
        __half2 h01 = __floats2half2_rn(hi32(acc[p][0]), hi32(acc[p][1]));
        __half2 h23 = __floats2half2_rn(hi32(acc[p][2]), hi32(acc[p][3]));
        uint2 lv, hv;
        lv.x = *reinterpret_cast<unsigned*>(&l01);
        lv.y = *reinterpret_cast<unsigned*>(&l23);
        hv.x = *reinterpret_cast<unsigned*>(&h01);
        hv.y = *reinterpret_cast<unsigned*>(&h23);
        if (n0 < NNODES) out2[(size_t)n0 * 32 + lane] = lv;
        if (n1 < NNODES) out2[(size_t)n1 * 32 + lane] = hv;
    }
}

// ---------------- aggregation: warp per node; 8-deep gather; fp16 in/out -----
__global__ void k_agg(const __half* __restrict__ h, __half* __restrict__ xo) {
    int gw = (blockIdx.x * blockDim.x + threadIdx.x) >> 5;
    int lane = threadIdx.x & 31;
    if (gw >= NNODES) return;
    int beg = g_off[gw], end = g_off[gw + 1];
    const uint2* h2 = (const uint2*)h;
    float4 accA = make_float4(0.f, 0.f, 0.f, 0.f);
    float4 accB = make_float4(0.f, 0.f, 0.f, 0.f);
    int e = beg;
    for (; e + 8 <= end; e += 8) {
        int   c[8];
        float m[8];
#pragma unroll
        for (int u = 0; u < 8; u++) { c[u] = g_ccol[e + u]; m[u] = g_cnrm[e + u]; }
        uint2 raw[8];
#pragma unroll
        for (int u = 0; u < 8; u++) raw[u] = h2[(size_t)c[u] * 32 + lane];
#pragma unroll
        for (int u = 0; u < 8; u += 2) {
            float4 v0 = h4_from_u2(raw[u]);
            float4 v1 = h4_from_u2(raw[u + 1]);
            accA.x = fmaf(m[u], v0.x, accA.x);
            accA.y = fmaf(m[u], v0.y, accA.y);
            accA.z = fmaf(m[u], v0.z, accA.z);
            accA.w = fmaf(m[u], v0.w, accA.w);
            accB.x = fmaf(m[u + 1], v1.x, accB.x);
            accB.y = fmaf(m[u + 1], v1.y, accB.y);
            accB.z = fmaf(m[u + 1], v1.z, accB.z);
            accB.w = fmaf(m[u + 1], v1.w, accB.w);
        }
    }
    for (; e < end; e++) {
        int cc = g_ccol[e];
        float nrm = g_cnrm[e];
        float4 v = h4_from_u2(h2[(size_t)cc * 32 + lane]);
        accA.x = fmaf(nrm, v.x, accA.x);
        accA.y = fmaf(nrm, v.y, accA.y);
        accA.z = fmaf(nrm, v.z, accA.z);
        accA.w = fmaf(nrm, v.w, accA.w);
    }
    __half2 p01 = __floats2half2_rn(fmaxf(accA.x + accB.x, 0.f), fmaxf(accA.y + accB.y, 0.f));
    __half2 p23 = __floats2half2_rn(fmaxf(accA.z + accB.z, 0.f), fmaxf(accA.w + accB.w, 0.f));
    uint2 v;
    v.x = *reinterpret_cast<unsigned*>(&p01);
    v.y = *reinterpret_cast<unsigned*>(&p23);
    ((uint2*)xo)[(size_t)gw * 32 + lane] = v;
}

// ---------------- fused pool + MLP head --------------------------------------
__device__ __forceinline__ int lbound(const void* b, int is64, long long key) {
    int lo = 0, hi = NNODES;
    while (lo < hi) {
        int mid = (lo + hi) >> 1;
        long long v = is64 ? ((const long long*)b)[mid] : (long long)((const int*)b)[mid];
        if (v < key) lo = mid + 1; else hi = mid;
    }
    return lo;
}

__global__ void k_pool_mlp(const void* batch,
                           const float* __restrict__ Wm1, const float* __restrict__ bm1,
                           const float* __restrict__ Wm2, const float* __restrict__ bm2,
                           float* __restrict__ out) {
    __shared__ float gs[2 * F];
    __shared__ float hs[F];
    int g = blockIdx.x, tid = threadIdx.x;
    int is64 = g_flags[1];
    int s = lbound(batch, is64, g);
    int e = lbound(batch, is64, g + 1);
    float sum = 0.f, mx = -3.4e38f;
    int n = s;
    for (; n + 2 <= e; n += 2) {
        float v0 = __half2float(g_x[(size_t)n * F + tid]);
        float v1 = __half2float(g_x[(size_t)(n + 1) * F + tid]);
        sum += v0 + v1;
        mx = fmaxf(mx, fmaxf(v0, v1));
    }
    for (; n < e; n++) {
        float v = __half2float(g_x[(size_t)n * F + tid]);
        sum += v;
        mx = fmaxf(mx, v);
    }
    int cnt = e - s;
    gs[tid] = sum / ((float)cnt + 1e-12f);
    gs[F + tid] = (cnt == 0) ? 0.f : mx;
    __syncthreads();
    float acc = bm1[tid];
#pragma unroll 8
    for (int k = 0; k < 2 * F; k++) acc = fmaf(gs[k], Wm1[k * F + tid], acc);
    hs[tid] = fmaxf(acc, 0.f);
    __syncthreads();
    if (tid < NC) {
        float a = bm2[tid];
#pragma unroll 8
        for (int k = 0; k < F; k++) a = fmaf(hs[k], Wm2[k * NC + tid], a);
        out[g * NC + tid] = a;
    }
}

// ---------------- launch ------------------------------------------------------
extern "C" void kernel_launch(void* const* d_in, const int* in_sizes, int n_in,
                              void* d_out, int out_size) {
    int iX = -1, iEI = -1, iB = -1, iW[3] = {-1, -1, -1}, ibv[4] = {-1, -1, -1, -1};
    int nw = 0, nb = 0, iWm1 = -1, iWm2 = -1, ibm2 = -1;
    for (int i = 0; i < n_in; i++) {
        int s = in_sizes[i];
        if (s == NNODES * F) iX = i;
        else if (s == 2 * NEDGES) iEI = i;
        else if (s == NNODES) iB = i;
        else if (s == F * F) { if (nw < 3) iW[nw++] = i; }
        else if (s == F) { if (nb < 4) ibv[nb++] = i; }
        else if (s == 2 * F * F) iWm1 = i;
        else if (s == F * NC) iWm2 = i;
        else if (s == NC) ibm2 = i;
    }
    const float* X   = (const float*)d_in[iX];
    const void*  EI  = d_in[iEI];
    const void*  BT  = d_in[iB];
    const float* W1  = (const float*)d_in[iW[0]];
    const float* W2  = (const float*)d_in[iW[1]];
    const float* W3  = (const float*)d_in[iW[2]];
    const float* b1  = (const float*)d_in[ibv[0]];
    const float* b2  = (const float*)d_in[ibv[1]];
    const float* b3  = (const float*)d_in[ibv[2]];
    const float* bm1 = (const float*)d_in[ibv[3]];
    const float* Wm1 = (const float*)d_in[iWm1];
    const float* Wm2 = (const float*)d_in[iWm2];
    const float* bm2 = (const float*)d_in[ibm2];
    float* out = (float*)d_out;

    void *ph = nullptr, *px = nullptr;
    cudaGetSymbolAddress(&ph, g_h);
    cudaGetSymbolAddress(&px, g_x);
    __half* H = (__half*)ph;
    __half* Xb = (__half*)px;

    size_t shm = (size_t)(F * F + F * XPAD) * sizeof(float);
    cudaFuncSetAttribute(k_gemm<false>, cudaFuncAttributeMaxDynamicSharedMemorySize, (int)shm);
    cudaFuncSetAttribute(k_gemm<true>, cudaFuncAttributeMaxDynamicSharedMemorySize, (int)shm);

    int gemm_grid = (NNODES + NB - 1) / NB;
    int agg_grid = (NNODES * 32 + 255) / 256;   // warp per node

    // Fork: layer-1 GEMM (depends only on X/W1) on s2, concurrent with CSR build.
    cudaEventRecord(evFork, 0);
    cudaStreamWaitEvent(s2, evFork, 0);
    k_gemm<false><<<gemm_grid, 256, shm, s2>>>(X, W1, b1, H);
    cudaEventRecord(evJoin, s2);

    // CSR preprocessing on the main stream
    k_detect<<<1, 1024>>>(EI, BT);
    k_hist<<<(NEDGES / 4 + 255) / 256, 256>>>(EI);
    k_scan1<<<NSB, SCAN_B>>>();
    k_scan2<<<1, 32>>>();
    k_scan3<<<NSB, SCAN_B>>>();
    k_fill<<<(NEDGES / 2 + 255) / 256, 256>>>(EI);
    k_fill_loops<<<(NNODES + 255) / 256, 256>>>();

    cudaStreamWaitEvent(0, evJoin, 0);

    k_agg<<<agg_grid, 256>>>(H, Xb);
    k_gemm<true><<<gemm_grid, 256, shm>>>(Xb, W2, b2, H);
    k_agg<<<agg_grid, 256>>>(H, Xb);
    k_gemm<true><<<gemm_grid, 256, shm>>>(Xb, W3, b3, H);
    k_agg<<<agg_grid, 256>>>(H, Xb);

    k_pool_mlp<<<NG, F>>>(BT, Wm1, bm1, Wm2, bm2, out);
}